// round 6
// baseline (speedup 1.0000x reference)
#include <cuda_runtime.h>
#include <math.h>
#include <stdint.h>

// Problem shape (fixed by setup_inputs)
#define BATCH 4
#define CDIM  512
#define NPTS  8192
#define KNN   16

// ---------------------------------------------------------------------------
// KNN kernel: one thread per query point. All candidates for the batch are
// cached in shared memory as float4(x, y, z, xx).
//
// Arithmetic replicates the reference's fp32 roundings exactly:
//   xx  = ((x*x) + (y*y)) + (z*z)          [elementwise square + l2r reduce]
//   dot = fma(z,z', fma(y,y', x*x'))       [k-ascending fma accumulate]
//   d   = fma(2, dot, -xx_n) - xx_m        [== (-xx_n - (-2*dot)) - xx_m]
// Top-16 kept as a sorted (desc) register list; strict '>' comparisons give
// jax.lax.top_k tie-breaking (lower index wins) since m scans ascending.
// ---------------------------------------------------------------------------
__global__ __launch_bounds__(256, 1)
void knn_kernel(const float* __restrict__ xyz, float* __restrict__ out_idx)
{
    extern __shared__ float4 sh[];
    const int b = blockIdx.y;
    const float* xb = xyz + (size_t)b * 3 * NPTS;

    for (int m = threadIdx.x; m < NPTS; m += blockDim.x) {
        float x = xb[m];
        float y = xb[NPTS + m];
        float z = xb[2 * NPTS + m];
        // reference order: ((x*x) + (y*y)) + (z*z), each op individually rounded
        float xx = __fadd_rn(__fadd_rn(__fmul_rn(x, x), __fmul_rn(y, y)),
                             __fmul_rn(z, z));
        sh[m] = make_float4(x, y, z, xx);
    }
    __syncthreads();

    const int n = blockIdx.x * blockDim.x + threadIdx.x;
    const float4 q = sh[n];
    const float nqxx = -q.w;

    float dk[KNN];
    int   ik[KNN];
#pragma unroll
    for (int j = 0; j < KNN; ++j) { dk[j] = -3.402823466e38f; ik[j] = 0; }

#pragma unroll 4
    for (int m = 0; m < NPTS; ++m) {
        float4 c = sh[m];
        // k-ascending fma accumulation (acc starts at exact product x*x')
        float dot = __fmaf_rn(q.z, c.z,
                    __fmaf_rn(q.y, c.y,
                    __fmul_rn(q.x, c.x)));
        // fma(2,dot,-xx_n) == round(-xx_n + 2*dot) == (-xx_n) - (-2*dot)
        float d = __fsub_rn(__fmaf_rn(2.0f, dot, nqxx), c.w);
        if (d > dk[KNN - 1]) {
            dk[KNN - 1] = d;
            ik[KNN - 1] = m;
#pragma unroll
            for (int j = KNN - 1; j > 0; --j) {
                // strict '>' : equal values keep earlier (lower-index) entry first
                if (dk[j] > dk[j - 1]) {
                    float td = dk[j]; dk[j] = dk[j - 1]; dk[j - 1] = td;
                    int   ti = ik[j]; ik[j] = ik[j - 1]; ik[j - 1] = ti;
                }
            }
        }
    }

    float* o = out_idx + ((size_t)b * NPTS + n) * KNN;
#pragma unroll
    for (int j = 0; j < KNN; ++j) o[j] = (float)ik[j];
}

// ---------------------------------------------------------------------------
// Fused dual GEMM + BN + ReLU + add:
//   enhanced = relu(bn_l(Wl @ F)) + relu(bn_g(Wg @ F))
// Block tile: 64 output rows x 128 cols. 256 threads as 16x16; each thread
// computes a 4x8 micro-tile for BOTH weight matrices (F tile loaded once,
// used twice -> 2x FMA per smem byte). K-tiles of 32, fp32 FFMA.
// ---------------------------------------------------------------------------
#define TM 64
#define TN 128
#define TK 32

__global__ __launch_bounds__(256, 2)
void fused_conv_kernel(const float* __restrict__ feat,
                       const float* __restrict__ wl,
                       const float* __restrict__ wg,
                       const float* __restrict__ gamma_l, const float* __restrict__ beta_l,
                       const float* __restrict__ mean_l,  const float* __restrict__ var_l,
                       const float* __restrict__ gamma_g, const float* __restrict__ beta_g,
                       const float* __restrict__ mean_g,  const float* __restrict__ var_g,
                       float* __restrict__ out)
{
    __shared__ __align__(16) float wl_s[TK][TM + 4];   // k-major (transposed)
    __shared__ __align__(16) float wg_s[TK][TM + 4];
    __shared__ __align__(16) float f_s[TK][TN + 4];

    const int b    = blockIdx.z;
    const int row0 = blockIdx.y * TM;
    const int col0 = blockIdx.x * TN;
    const int tid  = threadIdx.x;
    const int tx   = tid & 15;   // column group (8 cols)
    const int ty   = tid >> 4;   // row group (4 rows)

    const float* fb = feat + (size_t)b * CDIM * NPTS;

    float accl[4][8], accg[4][8];
#pragma unroll
    for (int i = 0; i < 4; ++i)
#pragma unroll
        for (int j = 0; j < 8; ++j) { accl[i][j] = 0.f; accg[i][j] = 0.f; }

    // W tile load mapping: 64 rows x 8 float4 = 512 float4 per W; 2 per thread.
    const int wrow  = tid >> 2;      // 0..63
    const int wcol4 = tid & 3;       // 0..3 (and +4 handled via +16 floats)
    // F tile load mapping: 32 rows x 32 float4 = 1024 float4; 4 per thread.
    const int fkrow = tid >> 3;      // 0..31
    const int fcol4 = tid & 7;       // 0..7

    for (int k0 = 0; k0 < CDIM; k0 += TK) {
        // --- load Wl / Wg tiles transposed into smem ---
        {
            const float* p = wl + (size_t)(row0 + wrow) * CDIM + k0 + wcol4 * 4;
            float4 v0 = *(const float4*)(p);
            float4 v1 = *(const float4*)(p + 16);
            int kc = wcol4 * 4;
            wl_s[kc + 0][wrow] = v0.x; wl_s[kc + 1][wrow] = v0.y;
            wl_s[kc + 2][wrow] = v0.z; wl_s[kc + 3][wrow] = v0.w;
            wl_s[kc + 16][wrow] = v1.x; wl_s[kc + 17][wrow] = v1.y;
            wl_s[kc + 18][wrow] = v1.z; wl_s[kc + 19][wrow] = v1.w;
        }
        {
            const float* p = wg + (size_t)(row0 + wrow) * CDIM + k0 + wcol4 * 4;
            float4 v0 = *(const float4*)(p);
            float4 v1 = *(const float4*)(p + 16);
            int kc = wcol4 * 4;
            wg_s[kc + 0][wrow] = v0.x; wg_s[kc + 1][wrow] = v0.y;
            wg_s[kc + 2][wrow] = v0.z; wg_s[kc + 3][wrow] = v0.w;
            wg_s[kc + 16][wrow] = v1.x; wg_s[kc + 17][wrow] = v1.y;
            wg_s[kc + 18][wrow] = v1.z; wg_s[kc + 19][wrow] = v1.w;
        }
        // --- load F tile ---
        {
            const float* p = fb + (size_t)(k0 + fkrow) * NPTS + col0;
#pragma unroll
            for (int r = 0; r < 4; ++r) {
                float4 v = *(const float4*)(p + (fcol4 + 8 * r) * 4);
                *(float4*)&f_s[fkrow][(fcol4 + 8 * r) * 4] = v;
            }
        }
        __syncthreads();

#pragma unroll 8
        for (int k = 0; k < TK; ++k) {
            float4 al = *(const float4*)&wl_s[k][ty * 4];
            float4 ag = *(const float4*)&wg_s[k][ty * 4];
            float4 b0 = *(const float4*)&f_s[k][tx * 8];
            float4 b1 = *(const float4*)&f_s[k][tx * 8 + 4];
            float bb[8]  = { b0.x, b0.y, b0.z, b0.w, b1.x, b1.y, b1.z, b1.w };
            float aal[4] = { al.x, al.y, al.z, al.w };
            float aag[4] = { ag.x, ag.y, ag.z, ag.w };
#pragma unroll
            for (int i = 0; i < 4; ++i)
#pragma unroll
                for (int j = 0; j < 8; ++j) {
                    accl[i][j] = __fmaf_rn(aal[i], bb[j], accl[i][j]);
                    accg[i][j] = __fmaf_rn(aag[i], bb[j], accg[i][j]);
                }
        }
        __syncthreads();
    }

    // --- epilogue: BN + ReLU for both branches, sum, store ---
#pragma unroll
    for (int i = 0; i < 4; ++i) {
        int r = row0 + ty * 4 + i;
        float sl = gamma_l[r] / sqrtf(var_l[r] + 1e-5f);
        float ol = beta_l[r] - mean_l[r] * sl;
        float sg = gamma_g[r] / sqrtf(var_g[r] + 1e-5f);
        float og = beta_g[r] - mean_g[r] * sg;
        float* orow = out + ((size_t)b * CDIM + r) * NPTS + col0 + tx * 8;
        float4 v0, v1;
        v0.x = fmaxf(accl[i][0] * sl + ol, 0.f) + fmaxf(accg[i][0] * sg + og, 0.f);
        v0.y = fmaxf(accl[i][1] * sl + ol, 0.f) + fmaxf(accg[i][1] * sg + og, 0.f);
        v0.z = fmaxf(accl[i][2] * sl + ol, 0.f) + fmaxf(accg[i][2] * sg + og, 0.f);
        v0.w = fmaxf(accl[i][3] * sl + ol, 0.f) + fmaxf(accg[i][3] * sg + og, 0.f);
        v1.x = fmaxf(accl[i][4] * sl + ol, 0.f) + fmaxf(accg[i][4] * sg + og, 0.f);
        v1.y = fmaxf(accl[i][5] * sl + ol, 0.f) + fmaxf(accg[i][5] * sg + og, 0.f);
        v1.z = fmaxf(accl[i][6] * sl + ol, 0.f) + fmaxf(accg[i][6] * sg + og, 0.f);
        v1.w = fmaxf(accl[i][7] * sl + ol, 0.f) + fmaxf(accg[i][7] * sg + og, 0.f);
        *(float4*)(orow)     = v0;
        *(float4*)(orow + 4) = v1;
    }
}

// ---------------------------------------------------------------------------
// Launch: out = [ enhanced (B,C,N) f32 | idx (B,N,K) as f32 ]
// ---------------------------------------------------------------------------
extern "C" void kernel_launch(void* const* d_in, const int* in_sizes, int n_in,
                              void* d_out, int out_size)
{
    const float* xyz     = (const float*)d_in[0];
    const float* feat    = (const float*)d_in[1];
    const float* wl      = (const float*)d_in[2];
    const float* gamma_l = (const float*)d_in[3];
    const float* beta_l  = (const float*)d_in[4];
    const float* mean_l  = (const float*)d_in[5];
    const float* var_l   = (const float*)d_in[6];
    const float* wg      = (const float*)d_in[7];
    const float* gamma_g = (const float*)d_in[8];
    const float* beta_g  = (const float*)d_in[9];
    const float* mean_g  = (const float*)d_in[10];
    const float* var_g   = (const float*)d_in[11];

    float* out     = (float*)d_out;
    float* out_idx = out + (size_t)BATCH * CDIM * NPTS;

    // 128 KB dynamic smem for the candidate cache (idempotent; capture-safe).
    cudaFuncSetAttribute(knn_kernel, cudaFuncAttributeMaxDynamicSharedMemorySize,
                         NPTS * (int)sizeof(float4));

    dim3 gknn(NPTS / 256, BATCH);
    knn_kernel<<<gknn, 256, NPTS * sizeof(float4)>>>(xyz, out_idx);

    dim3 gconv(NPTS / TN, CDIM / TM, BATCH);
    fused_conv_kernel<<<gconv, 256>>>(feat, wl, wg,
                                      gamma_l, beta_l, mean_l, var_l,
                                      gamma_g, beta_g, mean_g, var_g,
                                      out);
}

// round 10
// speedup vs baseline: 1.5814x; 1.5814x over previous
#include <cuda_runtime.h>
#include <cuda_fp16.h>
#include <math.h>
#include <stdint.h>

// Problem shape (fixed by setup_inputs)
#define BATCH 4
#define CDIM  512
#define NPTS  8192
#define KNN   16

// ===========================================================================
// helpers
// ===========================================================================
__device__ __forceinline__ uint32_t smem_to_u32(const void* p) {
    uint32_t a;
    asm("{ .reg .u64 t; cvta.to.shared.u64 t, %1; cvt.u32.u64 %0, t; }" : "=r"(a) : "l"(p));
    return a;
}
__device__ __forceinline__ uint32_t f22h(float a, float b) {
    __half2 h = __floats2half2_rn(a, b);
    return *reinterpret_cast<uint32_t*>(&h);
}
__device__ __forceinline__ void ldsm_x4(uint32_t& r0, uint32_t& r1, uint32_t& r2,
                                        uint32_t& r3, uint32_t addr) {
    asm volatile("ldmatrix.sync.aligned.m8n8.x4.shared.b16 {%0,%1,%2,%3}, [%4];"
                 : "=r"(r0), "=r"(r1), "=r"(r2), "=r"(r3) : "r"(addr));
}
__device__ __forceinline__ void ldsm_x2t(uint32_t& r0, uint32_t& r1, uint32_t addr) {
    asm volatile("ldmatrix.sync.aligned.m8n8.x2.trans.shared.b16 {%0,%1}, [%2];"
                 : "=r"(r0), "=r"(r1) : "r"(addr));
}
__device__ __forceinline__ void mma_f16(float* d, uint32_t a0, uint32_t a1,
                                        uint32_t a2, uint32_t a3,
                                        uint32_t b0, uint32_t b1) {
    asm volatile(
        "mma.sync.aligned.m16n8k16.row.col.f32.f16.f16.f32 "
        "{%0,%1,%2,%3}, {%4,%5,%6,%7}, {%8,%9}, {%0,%1,%2,%3};"
        : "+f"(d[0]), "+f"(d[1]), "+f"(d[2]), "+f"(d[3])
        : "r"(a0), "r"(a1), "r"(a2), "r"(a3), "r"(b0), "r"(b1));
}

// ===========================================================================
// KNN kernel: one thread per query; candidates staged in 32 KB smem chunks
// (2048 points/chunk, 4 chunks) -> 3 CTAs/SM resident (was 1 at 128 KB).
// Arithmetic replicates the reference's fp32 roundings exactly:
//   xx  = ((x*x) + (y*y)) + (z*z)
//   dot = fma(z,z', fma(y,y', x*x'))
//   d   = fma(2, dot, -xx_n) - xx_m
// Scan m ascending + strict '>' => jax.lax.top_k tie-break (lower index wins).
// ===========================================================================
#define KNN_CH 2048

__global__ __launch_bounds__(256, 3)
void knn_kernel(const float* __restrict__ xyz, float* __restrict__ out_idx)
{
    __shared__ float4 sh[KNN_CH];
    const int b = blockIdx.y;
    const float* xb = xyz + (size_t)b * 3 * NPTS;

    const int n = blockIdx.x * blockDim.x + threadIdx.x;
    float qx = xb[n], qy = xb[NPTS + n], qz = xb[2 * NPTS + n];
    const float nqxx = -__fadd_rn(__fadd_rn(__fmul_rn(qx, qx), __fmul_rn(qy, qy)),
                                  __fmul_rn(qz, qz));

    float dk[KNN];
    int   ik[KNN];
#pragma unroll
    for (int j = 0; j < KNN; ++j) { dk[j] = -3.402823466e38f; ik[j] = 0; }

    for (int c = 0; c < NPTS / KNN_CH; ++c) {
        const int base = c * KNN_CH;
        for (int m = threadIdx.x; m < KNN_CH; m += blockDim.x) {
            float x = xb[base + m];
            float y = xb[NPTS + base + m];
            float z = xb[2 * NPTS + base + m];
            float xx = __fadd_rn(__fadd_rn(__fmul_rn(x, x), __fmul_rn(y, y)),
                                 __fmul_rn(z, z));
            sh[m] = make_float4(x, y, z, xx);
        }
        __syncthreads();

#pragma unroll 4
        for (int mm = 0; mm < KNN_CH; ++mm) {
            float4 cd = sh[mm];
            float dot = __fmaf_rn(qz, cd.z, __fmaf_rn(qy, cd.y, __fmul_rn(qx, cd.x)));
            float d = __fsub_rn(__fmaf_rn(2.0f, dot, nqxx), cd.w);
            if (d > dk[KNN - 1]) {
                dk[KNN - 1] = d;
                ik[KNN - 1] = base + mm;
#pragma unroll
                for (int j = KNN - 1; j > 0; --j) {
                    if (dk[j] > dk[j - 1]) {
                        float td = dk[j]; dk[j] = dk[j - 1]; dk[j - 1] = td;
                        int   ti = ik[j]; ik[j] = ik[j - 1]; ik[j - 1] = ti;
                    }
                }
            }
        }
        __syncthreads();
    }

    float* o = out_idx + ((size_t)b * NPTS + n) * KNN;
#pragma unroll
    for (int j = 0; j < KNN; ++j) o[j] = (float)ik[j];
}

// ===========================================================================
// Dual fp16 mma.sync GEMM + BN + ReLU + add.
//   enhanced = relu(bn_l(Wl @ F)) + relu(bn_g(Wg @ F))
// CTA tile 128(M=channels) x 128(N=points); 8 warps, warp tile 64x32.
// K-tiles of 32 (2 ksteps of m16n8k16). Both GEMMs share the B (F) fragments.
// W staged k-contiguous (ldmatrix x4), F staged n-contiguous (ldmatrix x2.trans).
// Register prefetch of next K-tile's gmem loads hides latency under MMAs.
// ===========================================================================
#define KT 32
#define WPITCH 40    // halves per W smem row (80 B -> conflict-free ldmatrix)
#define FPITCH 136   // halves per F smem row (272 B -> conflict-free ldmatrix)
#define NKT (CDIM / KT)

__global__ __launch_bounds__(256, 1)
void gemm_mma_kernel(const float* __restrict__ feat,
                     const float* __restrict__ wl,
                     const float* __restrict__ wg,
                     const float* __restrict__ gamma_l, const float* __restrict__ beta_l,
                     const float* __restrict__ mean_l,  const float* __restrict__ var_l,
                     const float* __restrict__ gamma_g, const float* __restrict__ beta_g,
                     const float* __restrict__ mean_g,  const float* __restrict__ var_g,
                     float* __restrict__ out)
{
    __shared__ __align__(16) __half wl_s[128 * WPITCH];
    __shared__ __align__(16) __half wg_s[128 * WPITCH];
    __shared__ __align__(16) __half f_s[KT * FPITCH];
    __shared__ float sBN[4][128];

    const int tid  = threadIdx.x;
    const int wid  = tid >> 5;
    const int lane = tid & 31;

    const int col0 = blockIdx.x * 128;   // point base
    const int row0 = blockIdx.y * 128;   // channel base
    const int b    = blockIdx.z;

    // BN coefficient precompute (one channel per thread 0..127)
    if (tid < 128) {
        int r = row0 + tid;
        float sl = gamma_l[r] / sqrtf(var_l[r] + 1e-5f);
        sBN[0][tid] = sl;
        sBN[1][tid] = beta_l[r] - mean_l[r] * sl;
        float sg = gamma_g[r] / sqrtf(var_g[r] + 1e-5f);
        sBN[2][tid] = sg;
        sBN[3][tid] = beta_g[r] - mean_g[r] * sg;
    }

    const float* fb = feat + (size_t)b * CDIM * NPTS;

    // staging coords
    const int wm   = tid >> 1;          // W row 0..127
    const int wk16 = (tid & 1) * 16;    // W k offset 0/16
    const int fk   = tid >> 3;          // F k row 0..31
    const int fn16 = (tid & 7) * 16;    // F n offset

    const float* wlp = wl + (size_t)(row0 + wm) * CDIM + wk16;
    const float* wgp = wg + (size_t)(row0 + wm) * CDIM + wk16;
    const float* fp  = fb + (size_t)fk * NPTS + col0 + fn16;

    // ldmatrix base addresses
    const uint32_t wl_u = smem_to_u32(wl_s);
    const uint32_t wg_u = smem_to_u32(wg_s);
    const uint32_t f_u  = smem_to_u32(f_s);
    const int wmrow = (wid & 1) * 64;   // warp M offset
    const int wncol = (wid >> 1) * 32;  // warp N offset

    const uint32_t a_off = (uint32_t)((wmrow + (lane & 15)) * WPITCH + (lane >> 4) * 8) * 2;
    const uint32_t al_addr = wl_u + a_off;
    const uint32_t ag_addr = wg_u + a_off;
    const uint32_t b_addr  = f_u + (uint32_t)((lane & 15) * FPITCH + wncol) * 2;

    float d[2][4][4][4];
#pragma unroll
    for (int m = 0; m < 2; ++m)
#pragma unroll
        for (int i = 0; i < 4; ++i)
#pragma unroll
            for (int j = 0; j < 4; ++j)
#pragma unroll
                for (int q = 0; q < 4; ++q) d[m][i][j][q] = 0.f;

    uint32_t hl[8], hg[8], hf[8];

    // --- prefetch K-tile 0 ---
#define LDG_TILE(K0)                                                           \
    do {                                                                       \
        const float* p = wlp + (K0);                                           \
        float4 v0 = *(const float4*)(p),      v1 = *(const float4*)(p + 4);    \
        float4 v2 = *(const float4*)(p + 8),  v3 = *(const float4*)(p + 12);   \
        hl[0] = f22h(v0.x, v0.y); hl[1] = f22h(v0.z, v0.w);                    \
        hl[2] = f22h(v1.x, v1.y); hl[3] = f22h(v1.z, v1.w);                    \
        hl[4] = f22h(v2.x, v2.y); hl[5] = f22h(v2.z, v2.w);                    \
        hl[6] = f22h(v3.x, v3.y); hl[7] = f22h(v3.z, v3.w);                    \
        p = wgp + (K0);                                                        \
        v0 = *(const float4*)(p);      v1 = *(const float4*)(p + 4);           \
        v2 = *(const float4*)(p + 8);  v3 = *(const float4*)(p + 12);          \
        hg[0] = f22h(v0.x, v0.y); hg[1] = f22h(v0.z, v0.w);                    \
        hg[2] = f22h(v1.x, v1.y); hg[3] = f22h(v1.z, v1.w);                    \
        hg[4] = f22h(v2.x, v2.y); hg[5] = f22h(v2.z, v2.w);                    \
        hg[6] = f22h(v3.x, v3.y); hg[7] = f22h(v3.z, v3.w);                    \
        p = fp + (size_t)(K0) * NPTS;                                          \
        v0 = *(const float4*)(p);      v1 = *(const float4*)(p + 4);           \
        v2 = *(const float4*)(p + 8);  v3 = *(const float4*)(p + 12);          \
        hf[0] = f22h(v0.x, v0.y); hf[1] = f22h(v0.z, v0.w);                    \
        hf[2] = f22h(v1.x, v1.y); hf[3] = f22h(v1.z, v1.w);                    \
        hf[4] = f22h(v2.x, v2.y); hf[5] = f22h(v2.z, v2.w);                    \
        hf[6] = f22h(v3.x, v3.y); hf[7] = f22h(v3.z, v3.w);                    \
    } while (0)

    LDG_TILE(0);

    for (int kc = 0; kc < NKT; ++kc) {
        // ---- store staged registers to smem ----
        *(uint4*)&wl_s[wm * WPITCH + wk16]     = make_uint4(hl[0], hl[1], hl[2], hl[3]);
        *(uint4*)&wl_s[wm * WPITCH + wk16 + 8] = make_uint4(hl[4], hl[5], hl[6], hl[7]);
        *(uint4*)&wg_s[wm * WPITCH + wk16]     = make_uint4(hg[0], hg[1], hg[2], hg[3]);
        *(uint4*)&wg_s[wm * WPITCH + wk16 + 8] = make_uint4(hg[4], hg[5], hg[6], hg[7]);
        *(uint4*)&f_s[fk * FPITCH + fn16]      = make_uint4(hf[0], hf[1], hf[2], hf[3]);
        *(uint4*)&f_s[fk * FPITCH + fn16 + 8]  = make_uint4(hf[4], hf[5], hf[6], hf[7]);
        __syncthreads();

        // ---- prefetch next K-tile (latency hidden under the MMAs below) ----
        if (kc + 1 < NKT) LDG_TILE((kc + 1) * KT);

        // ---- MMA over 2 ksteps of k=16 ----
#pragma unroll
        for (int ks = 0; ks < 2; ++ks) {
            uint32_t b0[4], b1[4];
#pragma unroll
            for (int nf = 0; nf < 4; ++nf)
                ldsm_x2t(b0[nf], b1[nf],
                         b_addr + (uint32_t)(ks * 16 * FPITCH + nf * 8) * 2);
#pragma unroll
            for (int mf = 0; mf < 4; ++mf) {
                uint32_t a0, a1, a2, a3;
                ldsm_x4(a0, a1, a2, a3,
                        al_addr + (uint32_t)(mf * 16 * WPITCH) * 2 + ks * 32);
#pragma unroll
                for (int nf = 0; nf < 4; ++nf)
                    mma_f16(d[0][mf][nf], a0, a1, a2, a3, b0[nf], b1[nf]);
                ldsm_x4(a0, a1, a2, a3,
                        ag_addr + (uint32_t)(mf * 16 * WPITCH) * 2 + ks * 32);
#pragma unroll
                for (int nf = 0; nf < 4; ++nf)
                    mma_f16(d[1][mf][nf], a0, a1, a2, a3, b0[nf], b1[nf]);
            }
        }
        __syncthreads();
    }

    // ---- epilogue: BN + ReLU both branches, add, store ----
    const int g = lane >> 2;
    const int t = lane & 3;
#pragma unroll
    for (int mf = 0; mf < 4; ++mf) {
#pragma unroll
        for (int rr = 0; rr < 2; ++rr) {
            int rloc = wmrow + mf * 16 + g + rr * 8;     // channel within tile
            float sl = sBN[0][rloc], ol = sBN[1][rloc];
            float sg = sBN[2][rloc], og = sBN[3][rloc];
            float* orow = out + ((size_t)b * CDIM + row0 + rloc) * NPTS
                              + col0 + wncol + t * 2;
#pragma unroll
            for (int nf = 0; nf < 4; ++nf) {
                float2 v;
                v.x = fmaxf(d[0][mf][nf][rr * 2 + 0] * sl + ol, 0.f)
                    + fmaxf(d[1][mf][nf][rr * 2 + 0] * sg + og, 0.f);
                v.y = fmaxf(d[0][mf][nf][rr * 2 + 1] * sl + ol, 0.f)
                    + fmaxf(d[1][mf][nf][rr * 2 + 1] * sg + og, 0.f);
                *(float2*)(orow + nf * 8) = v;
            }
        }
    }
}

// ---------------------------------------------------------------------------
// Launch: out = [ enhanced (B,C,N) f32 | idx (B,N,K) as f32 ]
// ---------------------------------------------------------------------------
extern "C" void kernel_launch(void* const* d_in, const int* in_sizes, int n_in,
                              void* d_out, int out_size)
{
    const float* xyz     = (const float*)d_in[0];
    const float* feat    = (const float*)d_in[1];
    const float* wl      = (const float*)d_in[2];
    const float* gamma_l = (const float*)d_in[3];
    const float* beta_l  = (const float*)d_in[4];
    const float* mean_l  = (const float*)d_in[5];
    const float* var_l   = (const float*)d_in[6];
    const float* wg      = (const float*)d_in[7];
    const float* gamma_g = (const float*)d_in[8];
    const float* beta_g  = (const float*)d_in[9];
    const float* mean_g  = (const float*)d_in[10];
    const float* var_g   = (const float*)d_in[11];

    float* out     = (float*)d_out;
    float* out_idx = out + (size_t)BATCH * CDIM * NPTS;

    dim3 gg(NPTS / 128, CDIM / 128, BATCH);
    gemm_mma_kernel<<<gg, 256>>>(feat, wl, wg,
                                 gamma_l, beta_l, mean_l, var_l,
                                 gamma_g, beta_g, mean_g, var_g,
                                 out);

    dim3 gk(NPTS / 256, BATCH);
    knn_kernel<<<gk, 256>>>(xyz, out_idx);
}